// round 5
// baseline (speedup 1.0000x reference)
#include <cuda_runtime.h>
#include <math.h>
#include <stdint.h>

#define NN_ 100000
#define NE_ 3200000
#define MF 266
#define MP 272
#define DN_SCALE 0.35355339059327373f
#define RATIO 0.061313904565226276f
#define FEPS 1e-4f

__device__ __align__(16) float g_Wcat[1024 * 256];
__device__ float g_bcat[1024];
__device__ __align__(16) float g_qkvg[(size_t)NN_ * 1024];
__device__ __align__(16) float g_dd[(size_t)8 * NN_ * MP];
__device__ float g_diag[8 * NN_];
__device__ __align__(16) float g_ctx[4 * 320 * 80];
__device__ unsigned g_kmax[4];
__device__ __align__(16) float g_cat[(size_t)NN_ * 512];
__device__ __align__(16) float g_gnn2[(size_t)NN_ * 32];
__device__ __align__(16) float g_xa[(size_t)NN_ * 32];
__device__ __align__(16) float g_xb[(size_t)NN_ * 32];
__device__ int g_srci[NE_];
__device__ int g_dsti[NE_];
__device__ int g_csr_src[NE_];
__device__ float g_csr_w[NE_];
__device__ int g_cnt[NN_];
__device__ int g_cur[NN_];
__device__ int g_rowstart[NN_ + 1];
__device__ float g_dis[NN_];
__device__ float g_selfw[NN_];
__device__ int g_eflag[1];

__device__ __forceinline__ unsigned fenc(float f) {
    unsigned b = __float_as_uint(f);
    return b ^ ((b >> 31) ? 0xFFFFFFFFu : 0x80000000u);
}
__device__ __forceinline__ float fdec(unsigned u) {
    unsigned b = u ^ ((u >> 31) ? 0x80000000u : 0xFFFFFFFFu);
    return __uint_as_float(b);
}
__device__ __forceinline__ float eluf(float v) { return v > 0.f ? v : expm1f(v); }

__device__ __forceinline__ void tf32split(float a, float& hi, float& lo) {
    unsigned u;
    asm("cvt.rna.tf32.f32 %0, %1;" : "=r"(u) : "f"(a));
    hi = __uint_as_float(u);
    float r = a - hi;
    asm("cvt.rna.tf32.f32 %0, %1;" : "=r"(u) : "f"(r));
    lo = __uint_as_float(u);
}
__device__ __forceinline__ void mma8(float* d, const unsigned* a, unsigned b0, unsigned b1) {
    asm volatile(
        "mma.sync.aligned.m16n8k8.row.col.f32.tf32.tf32.f32 "
        "{%0,%1,%2,%3},{%4,%5,%6,%7},{%8,%9},{%0,%1,%2,%3};"
        : "+f"(d[0]), "+f"(d[1]), "+f"(d[2]), "+f"(d[3])
        : "r"(a[0]), "r"(a[1]), "r"(a[2]), "r"(a[3]), "r"(b0), "r"(b1));
}

// ---- edges / CSR ----
__global__ void sniff_edges(const void* ei) {
    if (threadIdx.x == 0) {
        const long long* p = (const long long*)ei;
        int bad = 0;
        for (int i = 0; i < 1000; i++) {
            long long v = p[i];
            if (v < 0 || v >= NN_) bad = 1;
        }
        g_eflag[0] = bad;
    }
}
__global__ void zero_i(int* p, int n) {
    int i = blockIdx.x * blockDim.x + threadIdx.x;
    if (i < n) p[i] = 0;
}
__global__ void conv_edges(const void* ei) {
    int e = blockIdx.x * blockDim.x + threadIdx.x;
    if (e >= NE_) return;
    int s, d;
    if (g_eflag[0]) {
        const int* p = (const int*)ei;
        s = p[e]; d = p[NE_ + e];
    } else {
        const long long* p = (const long long*)ei;
        s = (int)p[e]; d = (int)p[NE_ + e];
    }
    g_srci[e] = s;
    g_dsti[e] = d;
    atomicAdd(&g_cnt[d], 1);
}
__global__ void scan_kernel() {
    __shared__ int sh[1024];
    __shared__ int carry;
    int tid = threadIdx.x;
    if (tid == 0) carry = 0;
    __syncthreads();
    for (int base = 0; base < NN_; base += 1024) {
        int i = base + tid;
        int v = (i < NN_) ? g_cnt[i] : 0;
        sh[tid] = v;
        __syncthreads();
        for (int o = 1; o < 1024; o <<= 1) {
            int t = (tid >= o) ? sh[tid - o] : 0;
            __syncthreads();
            sh[tid] += t;
            __syncthreads();
        }
        if (i < NN_) g_rowstart[i] = carry + sh[tid] - v;
        __syncthreads();
        if (tid == 1023) carry += sh[1023];
        __syncthreads();
    }
    if (tid == 0) g_rowstart[NN_] = NE_;
}
__global__ void dis_kernel() {
    int n = blockIdx.x * blockDim.x + threadIdx.x;
    if (n >= NN_) return;
    float d = (float)(g_cnt[n] + 1);
    g_dis[n] = rsqrtf(d);
    g_selfw[n] = 0.9f / d;
}
__global__ void fill_csr() {
    int e = blockIdx.x * blockDim.x + threadIdx.x;
    if (e >= NE_) return;
    int s = g_srci[e], d = g_dsti[e];
    int pos = g_rowstart[d] + atomicAdd(&g_cur[d], 1);
    g_csr_src[pos] = s;
    g_csr_w[pos] = 0.9f * g_dis[s] * g_dis[d];
}

// ---- APPNP gather ----
__global__ void __launch_bounds__(256)
appnp_gather(const float* __restrict__ x, float* __restrict__ y) {
    long t = (long)blockIdx.x * blockDim.x + threadIdx.x;
    long n = t >> 3;
    int sub = (int)(t & 7);
    if (n >= NN_) return;
    int p0 = g_rowstart[n], p1 = g_rowstart[n + 1];
    const float4* x4 = (const float4*)x;
    float4 acc = make_float4(0.f, 0.f, 0.f, 0.f);
    for (int p = p0; p < p1; p++) {
        int s = g_csr_src[p];
        float w = g_csr_w[p];
        float4 xv = x4[(size_t)s * 8 + sub];
        acc.x += w * xv.x; acc.y += w * xv.y;
        acc.z += w * xv.z; acc.w += w * xv.w;
    }
    float sw = g_selfw[n];
    float4 xn = x4[(size_t)n * 8 + sub];
    float4 h = ((const float4*)g_gnn2)[(size_t)n * 8 + sub];
    float4 r;
    r.x = acc.x + sw * xn.x + 0.1f * h.x;
    r.y = acc.y + sw * xn.y + 0.1f * h.y;
    r.z = acc.z + sw * xn.z + 0.1f * h.z;
    r.w = acc.w + sw * xn.w + 0.1f * h.w;
    ((float4*)y)[(size_t)n * 8 + sub] = r;
}

__global__ void build_wcat(const float* __restrict__ qw, const float* __restrict__ kw,
                           const float* __restrict__ vw, const float* __restrict__ l1w,
                           const float* __restrict__ qb, const float* __restrict__ kb,
                           const float* __restrict__ vb, const float* __restrict__ l1b) {
    int idx = blockIdx.x * blockDim.x + threadIdx.x;
    if (idx >= 1024 * 256) return;
    int j = idx >> 8, k = idx & 255;
    const float* sw = (j < 256) ? qw : (j < 512) ? kw : (j < 768) ? vw : l1w;
    const float* sb = (j < 256) ? qb : (j < 512) ? kb : (j < 768) ? vb : l1b;
    g_Wcat[idx] = sw[(j & 255) * 256 + k];
    if (k == 0) g_bcat[j] = sb[j & 255];
}

// ---- tf32 tensor-core NT GEMM with 3-term precision split ----
// C = epi(alpha*A@B^T + bias); BM=128 BN=128 BK=16, 256 thr, 8 warps (4m x 2n)
// MODE: 0 plain, 1 elu, 2 qkv-special (mirror cols>=768 to g_cat with elu)
template <int MODE>
__global__ void __launch_bounds__(256)
gemm_tf32(const float* __restrict__ A, int lda, long sAz,
          const float* __restrict__ B, int ldb, long sBz,
          float* __restrict__ C, int ldc, long sCz,
          int M, int Ncols, int K, const float* __restrict__ bias, float alpha) {
    __shared__ float Ah[16][136], Al[16][136], Bh[16][136], Bl[16][136];
    int z = blockIdx.z;
    A += (long)z * sAz; B += (long)z * sBz; C += (long)z * sCz;
    int m0 = blockIdx.x * 128, n0 = blockIdx.y * 128;
    int tid = threadIdx.x;
    int warp = tid >> 5, lane = tid & 31;
    int wm = warp >> 1, wn = warp & 1;
    int g = lane >> 2, c4 = lane & 3;
    int lr = tid >> 2, lk = (tid & 3) * 4;
    float acc[2][8][4];
#pragma unroll
    for (int a = 0; a < 2; a++)
#pragma unroll
        for (int b = 0; b < 8; b++)
#pragma unroll
            for (int cc = 0; cc < 4; cc++) acc[a][b][cc] = 0.f;

    for (int k0 = 0; k0 < K; k0 += 16) {
#pragma unroll
        for (int p = 0; p < 2; p++) {
            int m = m0 + lr + 64 * p;
            float4 v = make_float4(0, 0, 0, 0);
            if (m < M) v = *(const float4*)(A + (size_t)m * lda + k0 + lk);
            float hi, lo;
            tf32split(v.x, hi, lo); Ah[lk + 0][lr + 64 * p] = hi; Al[lk + 0][lr + 64 * p] = lo;
            tf32split(v.y, hi, lo); Ah[lk + 1][lr + 64 * p] = hi; Al[lk + 1][lr + 64 * p] = lo;
            tf32split(v.z, hi, lo); Ah[lk + 2][lr + 64 * p] = hi; Al[lk + 2][lr + 64 * p] = lo;
            tf32split(v.w, hi, lo); Ah[lk + 3][lr + 64 * p] = hi; Al[lk + 3][lr + 64 * p] = lo;
        }
#pragma unroll
        for (int p = 0; p < 2; p++) {
            int n = n0 + lr + 64 * p;
            float4 v = make_float4(0, 0, 0, 0);
            if (n < Ncols) v = *(const float4*)(B + (size_t)n * ldb + k0 + lk);
            float hi, lo;
            tf32split(v.x, hi, lo); Bh[lk + 0][lr + 64 * p] = hi; Bl[lk + 0][lr + 64 * p] = lo;
            tf32split(v.y, hi, lo); Bh[lk + 1][lr + 64 * p] = hi; Bl[lk + 1][lr + 64 * p] = lo;
            tf32split(v.z, hi, lo); Bh[lk + 2][lr + 64 * p] = hi; Bl[lk + 2][lr + 64 * p] = lo;
            tf32split(v.w, hi, lo); Bh[lk + 3][lr + 64 * p] = hi; Bl[lk + 3][lr + 64 * p] = lo;
        }
        __syncthreads();
#pragma unroll
        for (int ks = 0; ks < 2; ks++) {
            int kb = ks * 8;
            unsigned ah[2][4], al[2][4];
#pragma unroll
            for (int mt = 0; mt < 2; mt++) {
                int mr = wm * 32 + mt * 16;
                ah[mt][0] = __float_as_uint(Ah[kb + c4][mr + g]);
                ah[mt][1] = __float_as_uint(Ah[kb + c4][mr + g + 8]);
                ah[mt][2] = __float_as_uint(Ah[kb + c4 + 4][mr + g]);
                ah[mt][3] = __float_as_uint(Ah[kb + c4 + 4][mr + g + 8]);
                al[mt][0] = __float_as_uint(Al[kb + c4][mr + g]);
                al[mt][1] = __float_as_uint(Al[kb + c4][mr + g + 8]);
                al[mt][2] = __float_as_uint(Al[kb + c4 + 4][mr + g]);
                al[mt][3] = __float_as_uint(Al[kb + c4 + 4][mr + g + 8]);
            }
#pragma unroll
            for (int nt = 0; nt < 8; nt++) {
                int nc = wn * 64 + nt * 8 + g;
                unsigned bh0 = __float_as_uint(Bh[kb + c4][nc]);
                unsigned bh1 = __float_as_uint(Bh[kb + c4 + 4][nc]);
                unsigned bl0 = __float_as_uint(Bl[kb + c4][nc]);
                unsigned bl1 = __float_as_uint(Bl[kb + c4 + 4][nc]);
#pragma unroll
                for (int mt = 0; mt < 2; mt++) {
                    mma8(acc[mt][nt], ah[mt], bh0, bh1);
                    mma8(acc[mt][nt], ah[mt], bl0, bl1);
                    mma8(acc[mt][nt], al[mt], bh0, bh1);
                }
            }
        }
        __syncthreads();
    }
#pragma unroll
    for (int mt = 0; mt < 2; mt++) {
#pragma unroll
        for (int nt = 0; nt < 8; nt++) {
#pragma unroll
            for (int half = 0; half < 2; half++) {
                int m = m0 + wm * 32 + mt * 16 + g + 8 * half;
                if (m >= M) continue;
#pragma unroll
                for (int cc = 0; cc < 2; cc++) {
                    int n = n0 + wn * 64 + nt * 8 + 2 * c4 + cc;
                    if (n >= Ncols) continue;
                    float v = acc[mt][nt][2 * half + cc] * alpha + (bias ? bias[n] : 0.f);
                    if (MODE == 1) v = eluf(v);
                    C[(size_t)m * ldc + n] = v;
                    if (MODE == 2 && n >= 768)
                        g_cat[(size_t)m * 512 + (n - 768)] = eluf(v);
                }
            }
        }
    }
}

__global__ void diag_kernel() {
    int gw = (blockIdx.x * blockDim.x + threadIdx.x) >> 5;
    int lane = threadIdx.x & 31;
    if (gw >= 8 * NN_) return;
    int s = gw / NN_, n = gw % NN_;
    const float* row = g_qkvg + (size_t)n * 1024 + s * 64;
    float v0 = row[lane], v1 = row[lane + 32];
    float sum = v0 * v0 + v1 * v1;
#pragma unroll
    for (int o = 16; o > 0; o >>= 1) sum += __shfl_xor_sync(~0u, sum, o);
    if (lane == 0) g_diag[s * NN_ + n] = 0.0625f * sum;
}

__global__ void qp_kernel() {
    int gw = (blockIdx.x * blockDim.x + threadIdx.x) >> 5;
    int lane = threadIdx.x & 31;
    if (gw >= 4 * NN_) return;
    int s = gw / NN_, n = gw % NN_;
    float* row = g_dd + (size_t)s * NN_ * MP + (size_t)n * MP;
    float dg = g_diag[s * NN_ + n];
    float vals[9], mx = -INFINITY;
#pragma unroll
    for (int i = 0; i < 9; i++) {
        int m = lane + 32 * i;
        float v = (m < MF) ? row[m] : -INFINITY;
        vals[i] = v; mx = fmaxf(mx, v);
    }
#pragma unroll
    for (int o = 16; o > 0; o >>= 1) mx = fmaxf(mx, __shfl_xor_sync(~0u, mx, o));
#pragma unroll
    for (int i = 0; i < 9; i++) {
        int m = lane + 32 * i;
        if (m < MP) row[m] = (m < MF) ? RATIO * (expf(vals[i] - dg - mx) + FEPS) : 0.f;
    }
}

__global__ void kmax_init() { if (threadIdx.x < 4) g_kmax[threadIdx.x] = 0x007FFFFFu; }

__global__ void kmax_kernel() {
    __shared__ float smx[8];
    int h = blockIdx.y;
    const float* base = g_dd + (size_t)(4 + h) * NN_ * MP;
    int warp = threadIdx.x >> 5, lane = threadIdx.x & 31;
    float mx = -INFINITY;
    for (int r = 0; r < 8; r++) {
        int n = blockIdx.x * 64 + warp * 8 + r;
        if (n < NN_) {
            const float* row = base + (size_t)n * MP;
#pragma unroll
            for (int i = 0; i < 9; i++) {
                int m = lane + 32 * i;
                if (m < MF) mx = fmaxf(mx, row[m]);
            }
        }
    }
#pragma unroll
    for (int o = 16; o > 0; o >>= 1) mx = fmaxf(mx, __shfl_xor_sync(~0u, mx, o));
    if (lane == 0) smx[warp] = mx;
    __syncthreads();
    if (threadIdx.x == 0) {
        float m2 = smx[0];
        for (int i = 1; i < 8; i++) m2 = fmaxf(m2, smx[i]);
        atomicMax(&g_kmax[h], fenc(m2));
    }
}

__global__ void kp_kernel() {
    int gw = (blockIdx.x * blockDim.x + threadIdx.x) >> 5;
    int lane = threadIdx.x & 31;
    if (gw >= 4 * NN_) return;
    int s = gw / NN_, n = gw % NN_;
    float* row = g_dd + (size_t)(4 + s) * NN_ * MP + (size_t)n * MP;
    float dg = g_diag[(4 + s) * NN_ + n];
    float mx = fdec(g_kmax[s]);
#pragma unroll
    for (int i = 0; i < 9; i++) {
        int m = lane + 32 * i;
        if (m < MP) row[m] = (m < MF) ? RATIO * (expf(row[m] - dg - mx) + FEPS) : 0.f;
    }
}

__global__ void zero_f(float* p, int n) {
    int i = blockIdx.x * blockDim.x + threadIdx.x;
    if (i < n) p[i] = 0.f;
}

// ---- ctx[h][m][j] = sum_n kp[h][n][m] * vext[n][j]; j==64 ones column ----
__global__ void __launch_bounds__(256)
ctx_kernel(int kchunk) {
    __shared__ __align__(16) float As[16][66];
    __shared__ __align__(16) float Bs[16][80];
    int h = blockIdx.z;
    const float* A = g_dd + (size_t)(4 + h) * NN_ * MP;
    int m0 = blockIdx.x * 64;
    int kb = blockIdx.y * kchunk, ke = min(kb + kchunk, NN_);
    int tid = threadIdx.x, tx = tid & 15, ty = tid >> 4;
    float acc[4][5];
#pragma unroll
    for (int a = 0; a < 4; a++)
#pragma unroll
        for (int b = 0; b < 5; b++) acc[a][b] = 0.f;
    for (int kk = kb; kk < ke; kk += 16) {
        {
            int k = tid >> 4, f = tid & 15;
            int kr = kk + k;
            float4 v = make_float4(0, 0, 0, 0);
            if (kr < ke && (m0 + 4 * f + 3) < MP)
                v = *(const float4*)(A + (size_t)kr * MP + m0 + 4 * f);
            As[k][4 * f] = v.x; As[k][4 * f + 1] = v.y;
            As[k][4 * f + 2] = v.z; As[k][4 * f + 3] = v.w;
        }
#pragma unroll
        for (int q = 0; q < 5; q++) {
            int fi = tid + 256 * q;
            int kr2 = fi / 80, j = fi % 80;
            int krow = kk + kr2;
            float v = 0.f;
            if (krow < ke) {
                if (j < 64) v = g_qkvg[(size_t)krow * 1024 + 512 + h * 64 + j];
                else if (j == 64) v = 1.f;
            }
            Bs[kr2][j] = v;
        }
        __syncthreads();
#pragma unroll
        for (int k2 = 0; k2 < 16; k2++) {
            float ra[4], rb[5];
#pragma unroll
            for (int a = 0; a < 4; a++) ra[a] = As[k2][ty * 4 + a];
#pragma unroll
            for (int b = 0; b < 5; b++) rb[b] = Bs[k2][tx * 5 + b];
#pragma unroll
            for (int a = 0; a < 4; a++)
#pragma unroll
                for (int b = 0; b < 5; b++) acc[a][b] += ra[a] * rb[b];
        }
        __syncthreads();
    }
    float* Cb = g_ctx + (size_t)h * 320 * 80;
#pragma unroll
    for (int a = 0; a < 4; a++)
#pragma unroll
        for (int b = 0; b < 5; b++)
            atomicAdd(&Cb[(m0 + ty * 4 + a) * 80 + tx * 5 + b], acc[a][b]);
}

// ---- attn = (qp @ ctx) / den -> elu -> g_cat[:,256+64h+c] ----
__global__ void __launch_bounds__(128)
gemm_attn() {
    __shared__ __align__(16) float As[16][68];
    __shared__ __align__(16) float Bs[16][80];
    __shared__ float sden[64];
    int h = blockIdx.z;
    const float* A = g_dd + (size_t)h * NN_ * MP;
    const float* B = g_ctx + (size_t)h * 320 * 80;
    int m0 = blockIdx.x * 64;
    int tid = threadIdx.x, tx = tid & 15, ty = tid >> 4;
    int lr = tid >> 2, lk = (tid & 3) * 4;
    float acc[8][5];
#pragma unroll
    for (int j = 0; j < 8; j++)
#pragma unroll
        for (int i = 0; i < 5; i++) acc[j][i] = 0.f;
    for (int k0 = 0; k0 < MP; k0 += 16) {
#pragma unroll
        for (int p = 0; p < 2; p++) {
            int m = m0 + lr + 32 * p;
            float4 v = make_float4(0, 0, 0, 0);
            if (m < NN_) v = *(const float4*)(A + (size_t)m * MP + k0 + lk);
            As[lk][lr + 32 * p] = v.x; As[lk + 1][lr + 32 * p] = v.y;
            As[lk + 2][lr + 32 * p] = v.z; As[lk + 3][lr + 32 * p] = v.w;
        }
#pragma unroll
        for (int q = 0; q < 3; q++) {
            int f4 = tid + 128 * q;
            if (f4 < 320)
                *(float4*)(&Bs[0][0] + f4 * 4) = *(const float4*)(B + (size_t)k0 * 80 + f4 * 4);
        }
        __syncthreads();
#pragma unroll
        for (int k = 0; k < 16; k++) {
            float ra[8], rb[5];
#pragma unroll
            for (int j = 0; j < 8; j++) ra[j] = As[k][ty + 8 * j];
#pragma unroll
            for (int i = 0; i < 5; i++) rb[i] = Bs[k][tx * 5 + i];
#pragma unroll
            for (int j = 0; j < 8; j++)
#pragma unroll
                for (int i = 0; i < 5; i++) acc[j][i] += ra[j] * rb[i];
        }
        __syncthreads();
    }
    if (tx == 12) {
#pragma unroll
        for (int j = 0; j < 8; j++) sden[ty + 8 * j] = acc[j][4];
    }
    __syncthreads();
#pragma unroll
    for (int j = 0; j < 8; j++) {
        int m = m0 + ty + 8 * j;
        if (m >= NN_) continue;
        float dinv = 1.f / sden[ty + 8 * j];
#pragma unroll
        for (int i = 0; i < 5; i++) {
            int c = tx * 5 + i;
            if (c < 64) g_cat[(size_t)m * 512 + 256 + h * 64 + c] = eluf(acc[j][i] * dinv);
        }
    }
}

__global__ void logsm_kernel(float* out, int wr2) {
    long gw = ((long)blockIdx.x * blockDim.x + threadIdx.x) >> 5;
    int lane = threadIdx.x & 31;
    if (gw >= NN_) return;
    float v = g_xb[gw * 32 + lane];
    float mx = v;
#pragma unroll
    for (int o = 16; o > 0; o >>= 1) mx = fmaxf(mx, __shfl_xor_sync(~0u, mx, o));
    float e = expf(v - mx), se = e;
#pragma unroll
    for (int o = 16; o > 0; o >>= 1) se += __shfl_xor_sync(~0u, se, o);
    out[gw * 32 + lane] = v - mx - logf(se);
    if (wr2) out[(size_t)NN_ * 32 + gw * 32 + lane] = v;
}

extern "C" void kernel_launch(void* const* d_in, const int* in_sizes, int n_in,
                              void* d_out, int out_size) {
    const float* x = (const float*)d_in[0];
    const void* ei = d_in[1];
    const float* l1w = (const float*)d_in[2];
    const float* l1b = (const float*)d_in[3];
    const float* l2w = (const float*)d_in[4];
    const float* l2b = (const float*)d_in[5];
    const float* qw = (const float*)d_in[6];
    const float* qb = (const float*)d_in[7];
    const float* kw = (const float*)d_in[8];
    const float* kb = (const float*)d_in[9];
    const float* vw = (const float*)d_in[10];
    const float* vb = (const float*)d_in[11];
    const float* proj = (const float*)d_in[12];
    float* out = (float*)d_out;

    float* d_Wcat; cudaGetSymbolAddress((void**)&d_Wcat, g_Wcat);
    float* d_bcat; cudaGetSymbolAddress((void**)&d_bcat, g_bcat);
    float* d_qkvg; cudaGetSymbolAddress((void**)&d_qkvg, g_qkvg);
    float* d_dd; cudaGetSymbolAddress((void**)&d_dd, g_dd);
    float* d_ctx; cudaGetSymbolAddress((void**)&d_ctx, g_ctx);
    float* d_cat; cudaGetSymbolAddress((void**)&d_cat, g_cat);
    float* d_gnn2; cudaGetSymbolAddress((void**)&d_gnn2, g_gnn2);
    float* d_xa; cudaGetSymbolAddress((void**)&d_xa, g_xa);
    float* d_xb; cudaGetSymbolAddress((void**)&d_xb, g_xb);
    int* d_cnt; cudaGetSymbolAddress((void**)&d_cnt, g_cnt);
    int* d_cur; cudaGetSymbolAddress((void**)&d_cur, g_cur);

    // graph prep
    sniff_edges<<<1, 32>>>(ei);
    zero_i<<<(NN_ + 255) / 256, 256>>>(d_cnt, NN_);
    zero_i<<<(NN_ + 255) / 256, 256>>>(d_cur, NN_);
    conv_edges<<<(NE_ + 255) / 256, 256>>>(ei);
    scan_kernel<<<1, 1024>>>();
    dis_kernel<<<(NN_ + 255) / 256, 256>>>();
    fill_csr<<<(NE_ + 255) / 256, 256>>>();

    // dense pipeline (tensor-core GEMMs)
    build_wcat<<<(1024 * 256 + 255) / 256, 256>>>(qw, kw, vw, l1w, qb, kb, vb, l1b);
    gemm_tf32<2><<<dim3((NN_ + 127) / 128, 8, 1), 256>>>(
        x, 256, 0, d_Wcat, 256, 0, d_qkvg, 1024, 0, NN_, 1024, 256, d_bcat, 1.f);
    gemm_tf32<0><<<dim3((NN_ + 127) / 128, 3, 8), 256>>>(
        d_qkvg, 1024, 64, proj, 64, 0, d_dd, MP, (long)NN_ * MP, NN_, MF, 64, nullptr, DN_SCALE);
    diag_kernel<<<(8L * NN_ * 32 + 255) / 256, 256>>>();
    qp_kernel<<<(4L * NN_ * 32 + 255) / 256, 256>>>();
    kmax_init<<<1, 32>>>();
    kmax_kernel<<<dim3((NN_ + 63) / 64, 4, 1), 256>>>();
    kp_kernel<<<(4L * NN_ * 32 + 255) / 256, 256>>>();
    zero_f<<<(4 * 320 * 80 + 255) / 256, 256>>>(d_ctx, 4 * 320 * 80);
    int kchunk = (NN_ + 63) / 64;
    ctx_kernel<<<dim3(5, 64, 4), 256>>>(kchunk);
    gemm_attn<<<dim3((NN_ + 63) / 64, 1, 4), 128>>>();
    gemm_tf32<1><<<dim3((NN_ + 127) / 128, 1, 1), 256>>>(
        d_cat, 512, 0, l2w, 512, 0, d_gnn2, 32, 0, NN_, 32, 512, l2b, 1.f);

    // APPNP
    long nth = (long)NN_ * 8;
    const float* cur = d_gnn2;
    float* nxt = d_xa;
    for (int it = 0; it < 10; it++) {
        appnp_gather<<<(nth + 255) / 256, 256>>>(cur, nxt);
        if (it == 0) { cur = d_xa; nxt = d_xb; }
        else { const float* t = cur; cur = nxt; nxt = (float*)t; }
    }
    int wr2 = (out_size >= 2 * NN_ * 32) ? 1 : 0;
    logsm_kernel<<<((long)NN_ * 32 + 255) / 256, 256>>>(out, wr2);
}

// round 6
// speedup vs baseline: 1.1113x; 1.1113x over previous
#include <cuda_runtime.h>
#include <math.h>
#include <stdint.h>

#define NN_ 100000
#define NE_ 3200000
#define MF 266
#define MP 272
#define DN_SCALE 0.35355339059327373f
#define RATIO 0.061313904565226276f
#define FEPS 1e-4f

__device__ __align__(16) float g_Wcat[1024 * 256];
__device__ float g_bcat[1024];
__device__ __align__(16) float g_qkvg[(size_t)NN_ * 1024];
__device__ __align__(16) float g_dd[(size_t)8 * NN_ * MP];
__device__ float g_diag[8 * NN_];
__device__ __align__(16) float g_ctx[4 * 320 * 80];
__device__ unsigned g_kmax[4];
__device__ __align__(16) float g_cat[(size_t)NN_ * 512];
__device__ __align__(16) float g_gnn2[(size_t)NN_ * 32];
__device__ __align__(16) float g_xa[(size_t)NN_ * 32];
__device__ __align__(16) float g_xb[(size_t)NN_ * 32];
__device__ int g_srci[NE_];
__device__ int g_dsti[NE_];
__device__ int g_csr_src[NE_];
__device__ float g_csr_w[NE_];
__device__ int g_cnt[NN_];
__device__ int g_cur[NN_];
__device__ int g_rowstart[NN_ + 1];
__device__ float g_dis[NN_];
__device__ float g_selfw[NN_];
__device__ int g_eflag[1];

__device__ __forceinline__ unsigned fenc(float f) {
    unsigned b = __float_as_uint(f);
    return b ^ ((b >> 31) ? 0xFFFFFFFFu : 0x80000000u);
}
__device__ __forceinline__ float fdec(unsigned u) {
    unsigned b = u ^ ((u >> 31) ? 0x80000000u : 0xFFFFFFFFu);
    return __uint_as_float(b);
}
__device__ __forceinline__ float eluf(float v) { return v > 0.f ? v : expm1f(v); }

// ---- edges / CSR ----
__global__ void sniff_edges(const void* ei) {
    if (threadIdx.x == 0) {
        const long long* p = (const long long*)ei;
        int bad = 0;
        for (int i = 0; i < 1000; i++) {
            long long v = p[i];
            if (v < 0 || v >= NN_) bad = 1;
        }
        g_eflag[0] = bad;
    }
}
__global__ void zero_i(int* p, int n) {
    int i = blockIdx.x * blockDim.x + threadIdx.x;
    if (i < n) p[i] = 0;
}
__global__ void conv_edges(const void* ei) {
    int e = blockIdx.x * blockDim.x + threadIdx.x;
    if (e >= NE_) return;
    int s, d;
    if (g_eflag[0]) {
        const int* p = (const int*)ei;
        s = p[e]; d = p[NE_ + e];
    } else {
        const long long* p = (const long long*)ei;
        s = (int)p[e]; d = (int)p[NE_ + e];
    }
    g_srci[e] = s;
    g_dsti[e] = d;
    atomicAdd(&g_cnt[d], 1);
}
__global__ void scan_kernel() {
    __shared__ int sh[1024];
    __shared__ int carry;
    int tid = threadIdx.x;
    if (tid == 0) carry = 0;
    __syncthreads();
    for (int base = 0; base < NN_; base += 1024) {
        int i = base + tid;
        int v = (i < NN_) ? g_cnt[i] : 0;
        sh[tid] = v;
        __syncthreads();
        for (int o = 1; o < 1024; o <<= 1) {
            int t = (tid >= o) ? sh[tid - o] : 0;
            __syncthreads();
            sh[tid] += t;
            __syncthreads();
        }
        if (i < NN_) g_rowstart[i] = carry + sh[tid] - v;
        __syncthreads();
        if (tid == 1023) carry += sh[1023];
        __syncthreads();
    }
    if (tid == 0) g_rowstart[NN_] = NE_;
}
__global__ void dis_kernel() {
    int n = blockIdx.x * blockDim.x + threadIdx.x;
    if (n >= NN_) return;
    float d = (float)(g_cnt[n] + 1);
    g_dis[n] = rsqrtf(d);
    g_selfw[n] = 0.9f / d;
}
__global__ void fill_csr() {
    int e = blockIdx.x * blockDim.x + threadIdx.x;
    if (e >= NE_) return;
    int s = g_srci[e], d = g_dsti[e];
    int pos = g_rowstart[d] + atomicAdd(&g_cur[d], 1);
    g_csr_src[pos] = s;
    g_csr_w[pos] = 0.9f * g_dis[s] * g_dis[d];
}

// ---- APPNP gather ----
__global__ void __launch_bounds__(256)
appnp_gather(const float* __restrict__ x, float* __restrict__ y) {
    long t = (long)blockIdx.x * blockDim.x + threadIdx.x;
    long n = t >> 3;
    int sub = (int)(t & 7);
    if (n >= NN_) return;
    int p0 = g_rowstart[n], p1 = g_rowstart[n + 1];
    const float4* x4 = (const float4*)x;
    float4 acc = make_float4(0.f, 0.f, 0.f, 0.f);
    for (int p = p0; p < p1; p++) {
        int s = g_csr_src[p];
        float w = g_csr_w[p];
        float4 xv = x4[(size_t)s * 8 + sub];
        acc.x += w * xv.x; acc.y += w * xv.y;
        acc.z += w * xv.z; acc.w += w * xv.w;
    }
    float sw = g_selfw[n];
    float4 xn = x4[(size_t)n * 8 + sub];
    float4 h = ((const float4*)g_gnn2)[(size_t)n * 8 + sub];
    float4 r;
    r.x = acc.x + sw * xn.x + 0.1f * h.x;
    r.y = acc.y + sw * xn.y + 0.1f * h.y;
    r.z = acc.z + sw * xn.z + 0.1f * h.z;
    r.w = acc.w + sw * xn.w + 0.1f * h.w;
    ((float4*)y)[(size_t)n * 8 + sub] = r;
}

__global__ void build_wcat(const float* __restrict__ qw, const float* __restrict__ kw,
                           const float* __restrict__ vw, const float* __restrict__ l1w,
                           const float* __restrict__ qb, const float* __restrict__ kb,
                           const float* __restrict__ vb, const float* __restrict__ l1b) {
    int idx = blockIdx.x * blockDim.x + threadIdx.x;
    if (idx >= 1024 * 256) return;
    int j = idx >> 8, k = idx & 255;
    const float* sw = (j < 256) ? qw : (j < 512) ? kw : (j < 768) ? vw : l1w;
    const float* sb = (j < 256) ? qb : (j < 512) ? kb : (j < 768) ? vb : l1b;
    g_Wcat[idx] = sw[(j & 255) * 256 + k];
    if (k == 0) g_bcat[j] = sb[j & 255];
}

// ---- SIMT NT GEMM, vectorized smem reads ----
// C = epi(alpha*A@B^T + bias); BM=128 BN=64 BK=16, 128 thr, tile 8x8 via float4
// MODE: 0 plain, 1 elu, 2 qkv-special (mirror cols>=768 to g_cat with elu)
// kmaxp: if non-null and blockIdx.z>=4, atomicMax per-head max of written values
template <int MODE>
__global__ void __launch_bounds__(128)
gemm_nt(const float* __restrict__ A, int lda, long sAz,
        const float* __restrict__ B, int ldb, long sBz,
        float* __restrict__ C, int ldc, long sCz,
        int M, int Ncols, int K, const float* __restrict__ bias, float alpha,
        unsigned* kmaxp) {
    __shared__ __align__(16) float As[16][128];
    __shared__ __align__(16) float Bs[16][64];
    __shared__ float red[128];
    int z = blockIdx.z;
    A += (long)z * sAz; B += (long)z * sBz; C += (long)z * sCz;
    int m0 = blockIdx.x * 128, n0 = blockIdx.y * 64;
    int tid = threadIdx.x, tx = tid & 7, ty = tid >> 3;
    int lr = tid >> 2, lk = (tid & 3) * 4;
    float acc[8][8];
#pragma unroll
    for (int j = 0; j < 8; j++)
#pragma unroll
        for (int i = 0; i < 8; i++) acc[j][i] = 0.f;
    for (int k0 = 0; k0 < K; k0 += 16) {
#pragma unroll
        for (int p = 0; p < 4; p++) {
            int m = m0 + lr + 32 * p;
            float4 v = make_float4(0, 0, 0, 0);
            if (m < M) v = *(const float4*)(A + (size_t)m * lda + k0 + lk);
            As[lk][lr + 32 * p] = v.x; As[lk + 1][lr + 32 * p] = v.y;
            As[lk + 2][lr + 32 * p] = v.z; As[lk + 3][lr + 32 * p] = v.w;
        }
#pragma unroll
        for (int p = 0; p < 2; p++) {
            int n = n0 + lr + 32 * p;
            float4 v = make_float4(0, 0, 0, 0);
            if (n < Ncols) v = *(const float4*)(B + (size_t)n * ldb + k0 + lk);
            Bs[lk][lr + 32 * p] = v.x; Bs[lk + 1][lr + 32 * p] = v.y;
            Bs[lk + 2][lr + 32 * p] = v.z; Bs[lk + 3][lr + 32 * p] = v.w;
        }
        __syncthreads();
#pragma unroll
        for (int k = 0; k < 16; k++) {
            float4 a0 = *(const float4*)&As[k][ty * 4];
            float4 a1 = *(const float4*)&As[k][64 + ty * 4];
            float4 b0 = *(const float4*)&Bs[k][tx * 4];
            float4 b1 = *(const float4*)&Bs[k][32 + tx * 4];
            float ra[8] = {a0.x, a0.y, a0.z, a0.w, a1.x, a1.y, a1.z, a1.w};
            float rb[8] = {b0.x, b0.y, b0.z, b0.w, b1.x, b1.y, b1.z, b1.w};
#pragma unroll
            for (int j = 0; j < 8; j++)
#pragma unroll
                for (int i = 0; i < 8; i++) acc[j][i] += ra[j] * rb[i];
        }
        __syncthreads();
    }
    float mx = -INFINITY;
#pragma unroll
    for (int j = 0; j < 8; j++) {
        int m = m0 + ((j < 4) ? ty * 4 + j : 64 + ty * 4 + (j - 4));
        if (m >= M) continue;
#pragma unroll
        for (int i = 0; i < 8; i++) {
            int n = n0 + ((i < 4) ? tx * 4 + i : 32 + tx * 4 + (i - 4));
            if (n >= Ncols) continue;
            float v = acc[j][i] * alpha + (bias ? bias[n] : 0.f);
            if (MODE == 1) v = eluf(v);
            C[(size_t)m * ldc + n] = v;
            if (MODE == 2 && n >= 768)
                g_cat[(size_t)m * 512 + (n - 768)] = eluf(v);
            mx = fmaxf(mx, v);
        }
    }
    if (kmaxp && z >= 4) {
        red[tid] = mx;
        __syncthreads();
        for (int s = 64; s > 0; s >>= 1) {
            if (tid < s) red[tid] = fmaxf(red[tid], red[tid + s]);
            __syncthreads();
        }
        if (tid == 0) atomicMax(&kmaxp[z - 4], fenc(red[0]));
    }
}

__global__ void diag_kernel() {
    int gw = (blockIdx.x * blockDim.x + threadIdx.x) >> 5;
    int lane = threadIdx.x & 31;
    if (gw >= 8 * NN_) return;
    int s = gw / NN_, n = gw % NN_;
    const float* row = g_qkvg + (size_t)n * 1024 + s * 64;
    float v0 = row[lane], v1 = row[lane + 32];
    float sum = v0 * v0 + v1 * v1;
#pragma unroll
    for (int o = 16; o > 0; o >>= 1) sum += __shfl_xor_sync(~0u, sum, o);
    if (lane == 0) g_diag[s * NN_ + n] = 0.0625f * sum;
}

__global__ void qp_kernel() {
    int gw = (blockIdx.x * blockDim.x + threadIdx.x) >> 5;
    int lane = threadIdx.x & 31;
    if (gw >= 4 * NN_) return;
    int s = gw / NN_, n = gw % NN_;
    float* row = g_dd + (size_t)s * NN_ * MP + (size_t)n * MP;
    float dg = g_diag[s * NN_ + n];
    float vals[9], mx = -INFINITY;
#pragma unroll
    for (int i = 0; i < 9; i++) {
        int m = lane + 32 * i;
        float v = (m < MF) ? row[m] : -INFINITY;
        vals[i] = v; mx = fmaxf(mx, v);
    }
#pragma unroll
    for (int o = 16; o > 0; o >>= 1) mx = fmaxf(mx, __shfl_xor_sync(~0u, mx, o));
#pragma unroll
    for (int i = 0; i < 9; i++) {
        int m = lane + 32 * i;
        if (m < MP) row[m] = (m < MF) ? RATIO * (expf(vals[i] - dg - mx) + FEPS) : 0.f;
    }
}

__global__ void kmax_init() { if (threadIdx.x < 4) g_kmax[threadIdx.x] = 0x007FFFFFu; }

__global__ void kp_kernel() {
    int gw = (blockIdx.x * blockDim.x + threadIdx.x) >> 5;
    int lane = threadIdx.x & 31;
    if (gw >= 4 * NN_) return;
    int s = gw / NN_, n = gw % NN_;
    float* row = g_dd + (size_t)(4 + s) * NN_ * MP + (size_t)n * MP;
    float dg = g_diag[(4 + s) * NN_ + n];
    float mx = fdec(g_kmax[s]);
#pragma unroll
    for (int i = 0; i < 9; i++) {
        int m = lane + 32 * i;
        if (m < MP) row[m] = (m < MF) ? RATIO * (expf(row[m] - dg - mx) + FEPS) : 0.f;
    }
}

__global__ void zero_f(float* p, int n) {
    int i = blockIdx.x * blockDim.x + threadIdx.x;
    if (i < n) p[i] = 0.f;
}

// ---- ctx[h][m][j] = sum_n kp[h][n][m] * vext[n][j]; j==64 ones column ----
__global__ void __launch_bounds__(256)
ctx_kernel(int kchunk) {
    __shared__ __align__(16) float As[16][66];
    __shared__ __align__(16) float Bs[16][80];
    int h = blockIdx.z;
    const float* A = g_dd + (size_t)(4 + h) * NN_ * MP;
    int m0 = blockIdx.x * 64;
    int kb = blockIdx.y * kchunk, ke = min(kb + kchunk, NN_);
    int tid = threadIdx.x, tx = tid & 15, ty = tid >> 4;
    float acc[4][5];
#pragma unroll
    for (int a = 0; a < 4; a++)
#pragma unroll
        for (int b = 0; b < 5; b++) acc[a][b] = 0.f;
    for (int kk = kb; kk < ke; kk += 16) {
        {
            int k = tid >> 4, f = tid & 15;
            int kr = kk + k;
            float4 v = make_float4(0, 0, 0, 0);
            if (kr < ke && (m0 + 4 * f + 3) < MP)
                v = *(const float4*)(A + (size_t)kr * MP + m0 + 4 * f);
            As[k][4 * f] = v.x; As[k][4 * f + 1] = v.y;
            As[k][4 * f + 2] = v.z; As[k][4 * f + 3] = v.w;
        }
#pragma unroll
        for (int q = 0; q < 5; q++) {
            int fi = tid + 256 * q;
            int kr2 = fi / 80, j = fi % 80;
            int krow = kk + kr2;
            float v = 0.f;
            if (krow < ke) {
                if (j < 64) v = g_qkvg[(size_t)krow * 1024 + 512 + h * 64 + j];
                else if (j == 64) v = 1.f;
            }
            Bs[kr2][j] = v;
        }
        __syncthreads();
#pragma unroll
        for (int k2 = 0; k2 < 16; k2++) {
            float ra[4], rb[5];
#pragma unroll
            for (int a = 0; a < 4; a++) ra[a] = As[k2][ty * 4 + a];
#pragma unroll
            for (int b = 0; b < 5; b++) rb[b] = Bs[k2][tx * 5 + b];
#pragma unroll
            for (int a = 0; a < 4; a++)
#pragma unroll
                for (int b = 0; b < 5; b++) acc[a][b] += ra[a] * rb[b];
        }
        __syncthreads();
    }
    float* Cb = g_ctx + (size_t)h * 320 * 80;
#pragma unroll
    for (int a = 0; a < 4; a++)
#pragma unroll
        for (int b = 0; b < 5; b++)
            atomicAdd(&Cb[(m0 + ty * 4 + a) * 80 + tx * 5 + b], acc[a][b]);
}

// ---- attn = (qp @ ctx) / den -> elu -> g_cat[:,256+64h+c] ----
__global__ void __launch_bounds__(128)
gemm_attn() {
    __shared__ __align__(16) float As[16][64];
    __shared__ __align__(16) float Bs[16][80];
    __shared__ float sden[64];
    int h = blockIdx.z;
    const float* A = g_dd + (size_t)h * NN_ * MP;
    const float* B = g_ctx + (size_t)h * 320 * 80;
    int m0 = blockIdx.x * 64;
    int tid = threadIdx.x, tx = tid & 15, ty = tid >> 4;
    int lr = tid >> 2, lk = (tid & 3) * 4;
    float acc[8][5];
#pragma unroll
    for (int j = 0; j < 8; j++)
#pragma unroll
        for (int i = 0; i < 5; i++) acc[j][i] = 0.f;
    for (int k0 = 0; k0 < MP; k0 += 16) {
#pragma unroll
        for (int p = 0; p < 2; p++) {
            int m = m0 + lr + 32 * p;
            float4 v = make_float4(0, 0, 0, 0);
            if (m < NN_) v = *(const float4*)(A + (size_t)m * MP + k0 + lk);
            As[lk][lr + 32 * p] = v.x; As[lk + 1][lr + 32 * p] = v.y;
            As[lk + 2][lr + 32 * p] = v.z; As[lk + 3][lr + 32 * p] = v.w;
        }
#pragma unroll
        for (int q = 0; q < 3; q++) {
            int f4 = tid + 128 * q;
            if (f4 < 320)
                *(float4*)(&Bs[0][0] + f4 * 4) = *(const float4*)(B + (size_t)k0 * 80 + f4 * 4);
        }
        __syncthreads();
#pragma unroll
        for (int k = 0; k < 16; k++) {
            float4 a0 = *(const float4*)&As[k][ty * 4];
            float4 a1 = *(const float4*)&As[k][32 + ty * 4];
            float ra[8] = {a0.x, a0.y, a0.z, a0.w, a1.x, a1.y, a1.z, a1.w};
            float rb[5];
#pragma unroll
            for (int i = 0; i < 5; i++) rb[i] = Bs[k][tx * 5 + i];
#pragma unroll
            for (int j = 0; j < 8; j++)
#pragma unroll
                for (int i = 0; i < 5; i++) acc[j][i] += ra[j] * rb[i];
        }
        __syncthreads();
    }
    if (tx == 12) {
#pragma unroll
        for (int j = 0; j < 8; j++) {
            int rr = (j < 4) ? ty * 4 + j : 32 + ty * 4 + (j - 4);
            sden[rr] = acc[j][4];
        }
    }
    __syncthreads();
#pragma unroll
    for (int j = 0; j < 8; j++) {
        int rr = (j < 4) ? ty * 4 + j : 32 + ty * 4 + (j - 4);
        int m = m0 + rr;
        if (m >= NN_) continue;
        float dinv = 1.f / sden[rr];
#pragma unroll
        for (int i = 0; i < 5; i++) {
            int c = tx * 5 + i;
            if (c < 64) g_cat[(size_t)m * 512 + 256 + h * 64 + c] = eluf(acc[j][i] * dinv);
        }
    }
}

__global__ void logsm_kernel(float* out, int wr2) {
    long gw = ((long)blockIdx.x * blockDim.x + threadIdx.x) >> 5;
    int lane = threadIdx.x & 31;
    if (gw >= NN_) return;
    float v = g_xb[gw * 32 + lane];
    float mx = v;
#pragma unroll
    for (int o = 16; o > 0; o >>= 1) mx = fmaxf(mx, __shfl_xor_sync(~0u, mx, o));
    float e = expf(v - mx), se = e;
#pragma unroll
    for (int o = 16; o > 0; o >>= 1) se += __shfl_xor_sync(~0u, se, o);
    out[gw * 32 + lane] = v - mx - logf(se);
    if (wr2) out[(size_t)NN_ * 32 + gw * 32 + lane] = v;
}

extern "C" void kernel_launch(void* const* d_in, const int* in_sizes, int n_in,
                              void* d_out, int out_size) {
    const float* x = (const float*)d_in[0];
    const void* ei = d_in[1];
    const float* l1w = (const float*)d_in[2];
    const float* l1b = (const float*)d_in[3];
    const float* l2w = (const float*)d_in[4];
    const float* l2b = (const float*)d_in[5];
    const float* qw = (const float*)d_in[6];
    const float* qb = (const float*)d_in[7];
    const float* kw = (const float*)d_in[8];
    const float* kb = (const float*)d_in[9];
    const float* vw = (const float*)d_in[10];
    const float* vb = (const float*)d_in[11];
    const float* proj = (const float*)d_in[12];
    float* out = (float*)d_out;

    float* d_Wcat; cudaGetSymbolAddress((void**)&d_Wcat, g_Wcat);
    float* d_bcat; cudaGetSymbolAddress((void**)&d_bcat, g_bcat);
    float* d_qkvg; cudaGetSymbolAddress((void**)&d_qkvg, g_qkvg);
    float* d_dd; cudaGetSymbolAddress((void**)&d_dd, g_dd);
    float* d_ctx; cudaGetSymbolAddress((void**)&d_ctx, g_ctx);
    float* d_cat; cudaGetSymbolAddress((void**)&d_cat, g_cat);
    float* d_gnn2; cudaGetSymbolAddress((void**)&d_gnn2, g_gnn2);
    float* d_xa; cudaGetSymbolAddress((void**)&d_xa, g_xa);
    float* d_xb; cudaGetSymbolAddress((void**)&d_xb, g_xb);
    int* d_cnt; cudaGetSymbolAddress((void**)&d_cnt, g_cnt);
    int* d_cur; cudaGetSymbolAddress((void**)&d_cur, g_cur);
    unsigned* d_kmax; cudaGetSymbolAddress((void**)&d_kmax, g_kmax);

    // graph prep
    sniff_edges<<<1, 32>>>(ei);
    zero_i<<<(NN_ + 255) / 256, 256>>>(d_cnt, NN_);
    zero_i<<<(NN_ + 255) / 256, 256>>>(d_cur, NN_);
    conv_edges<<<(NE_ + 255) / 256, 256>>>(ei);
    scan_kernel<<<1, 1024>>>();
    dis_kernel<<<(NN_ + 255) / 256, 256>>>();
    fill_csr<<<(NE_ + 255) / 256, 256>>>();

    // dense pipeline
    build_wcat<<<(1024 * 256 + 255) / 256, 256>>>(qw, kw, vw, l1w, qb, kb, vb, l1b);
    gemm_nt<2><<<dim3((NN_ + 127) / 128, 16, 1), 128>>>(
        x, 256, 0, d_Wcat, 256, 0, d_qkvg, 1024, 0, NN_, 1024, 256, d_bcat, 1.f, nullptr);
    kmax_init<<<1, 32>>>();
    gemm_nt<0><<<dim3((NN_ + 127) / 128, 5, 8), 128>>>(
        d_qkvg, 1024, 64, proj, 64, 0, d_dd, MP, (long)NN_ * MP, NN_, MF, 64, nullptr,
        DN_SCALE, d_kmax);
    diag_kernel<<<(8L * NN_ * 32 + 255) / 256, 256>>>();
    qp_kernel<<<(4L * NN_ * 32 + 255) / 256, 256>>>();
    kp_kernel<<<(4L * NN_ * 32 + 255) / 256, 256>>>();
    zero_f<<<(4 * 320 * 80 + 255) / 256, 256>>>(d_ctx, 4 * 320 * 80);
    int kchunk = (NN_ + 63) / 64;
    ctx_kernel<<<dim3(5, 64, 4), 256>>>(kchunk);
    gemm_attn<<<dim3((NN_ + 63) / 64, 1, 4), 128>>>();
    gemm_nt<1><<<dim3((NN_ + 127) / 128, 1, 1), 128>>>(
        d_cat, 512, 0, l2w, 512, 0, d_gnn2, 32, 0, NN_, 32, 512, l2b, 1.f, nullptr);

    // APPNP
    long nth = (long)NN_ * 8;
    const float* cur = d_gnn2;
    float* nxt = d_xa;
    for (int it = 0; it < 10; it++) {
        appnp_gather<<<(nth + 255) / 256, 256>>>(cur, nxt);
        if (it == 0) { cur = d_xa; nxt = d_xb; }
        else { const float* t = cur; cur = nxt; nxt = (float*)t; }
    }
    int wr2 = (out_size >= 2 * NN_ * 32) ? 1 : 0;
    logsm_kernel<<<((long)NN_ * 32 + 255) / 256, 256>>>(out, wr2);
}

// round 7
// speedup vs baseline: 1.2074x; 1.0864x over previous
#include <cuda_runtime.h>
#include <math.h>
#include <stdint.h>

#define NN_ 100000
#define NE_ 3200000
#define MF 266
#define MP 272
#define NCHUNK ((NN_ + 1023) / 1024)
#define DN_SCALE 0.35355339059327373f
#define RATIO 0.061313904565226276f
#define FEPS 1e-4f

__device__ __align__(16) float g_Wcat[1024 * 256];
__device__ float g_bcat[1024];
__device__ __align__(16) float g_qkvg[(size_t)NN_ * 1024];
__device__ __align__(16) float g_dd[(size_t)8 * NN_ * MP];
__device__ float g_diag[8 * NN_];
__device__ __align__(16) float g_ctx[4 * 320 * 80];
__device__ unsigned g_kmax[4];
__device__ __align__(16) float g_cat[(size_t)NN_ * 512];
__device__ __align__(16) float g_gnn2[(size_t)NN_ * 32];
__device__ __align__(16) float g_xa[(size_t)NN_ * 32];
__device__ __align__(16) float g_xb[(size_t)NN_ * 32];
__device__ int g_srci[NE_];
__device__ int g_dsti[NE_];
__device__ int g_csr_src[NE_];
__device__ float g_csr_w[NE_];
__device__ int g_cnt[NN_];
__device__ int g_cur[NN_];
__device__ int g_rowstart[NN_ + 1];
__device__ int g_bsum[128];
__device__ float g_dis[NN_];
__device__ float g_selfw[NN_];
__device__ int g_eflag[1];

__device__ __forceinline__ unsigned fenc(float f) {
    unsigned b = __float_as_uint(f);
    return b ^ ((b >> 31) ? 0xFFFFFFFFu : 0x80000000u);
}
__device__ __forceinline__ float fdec(unsigned u) {
    unsigned b = u ^ ((u >> 31) ? 0x80000000u : 0xFFFFFFFFu);
    return __uint_as_float(b);
}
__device__ __forceinline__ float eluf(float v) { return v > 0.f ? v : expm1f(v); }

// ---- edges / CSR ----
__global__ void sniff_edges(const void* ei) {
    if (threadIdx.x == 0) {
        const long long* p = (const long long*)ei;
        int bad = 0;
        for (int i = 0; i < 1000; i++) {
            long long v = p[i];
            if (v < 0 || v >= NN_) bad = 1;
        }
        g_eflag[0] = bad;
    }
}
__global__ void zero_i(int* p, int n) {
    int i = blockIdx.x * blockDim.x + threadIdx.x;
    if (i < n) p[i] = 0;
}
__global__ void conv_edges(const void* ei) {
    int e = blockIdx.x * blockDim.x + threadIdx.x;
    if (e >= NE_) return;
    int s, d;
    if (g_eflag[0]) {
        const int* p = (const int*)ei;
        s = p[e]; d = p[NE_ + e];
    } else {
        const long long* p = (const long long*)ei;
        s = (int)p[e]; d = (int)p[NE_ + e];
    }
    g_srci[e] = s;
    g_dsti[e] = d;
    atomicAdd(&g_cnt[d], 1);
}
// parallel 3-phase exclusive scan of g_cnt -> g_rowstart
__global__ void scan1() {
    __shared__ int sh[1024];
    int b = blockIdx.x, tid = threadIdx.x;
    int i = b * 1024 + tid;
    int v = (i < NN_) ? g_cnt[i] : 0;
    sh[tid] = v;
    __syncthreads();
    for (int o = 1; o < 1024; o <<= 1) {
        int t = (tid >= o) ? sh[tid - o] : 0;
        __syncthreads();
        sh[tid] += t;
        __syncthreads();
    }
    if (i < NN_) g_rowstart[i] = sh[tid] - v;
    if (tid == 1023) g_bsum[b] = sh[1023];
}
__global__ void scan2() {
    __shared__ int sh[128];
    int tid = threadIdx.x;
    int v = (tid < NCHUNK) ? g_bsum[tid] : 0;
    sh[tid] = v;
    __syncthreads();
    for (int o = 1; o < 128; o <<= 1) {
        int t = (tid >= o) ? sh[tid - o] : 0;
        __syncthreads();
        sh[tid] += t;
        __syncthreads();
    }
    g_bsum[tid] = sh[tid] - v;  // exclusive
}
__global__ void scan3() {
    int i = blockIdx.x * blockDim.x + threadIdx.x;
    if (i < NN_) g_rowstart[i] += g_bsum[i >> 10];
    if (i == 0) g_rowstart[NN_] = NE_;
}
__global__ void dis_kernel() {
    int n = blockIdx.x * blockDim.x + threadIdx.x;
    if (n >= NN_) return;
    float d = (float)(g_cnt[n] + 1);
    g_dis[n] = rsqrtf(d);
    g_selfw[n] = 0.9f / d;
}
__global__ void fill_csr() {
    int e = blockIdx.x * blockDim.x + threadIdx.x;
    if (e >= NE_) return;
    int s = g_srci[e], d = g_dsti[e];
    int pos = g_rowstart[d] + atomicAdd(&g_cur[d], 1);
    g_csr_src[pos] = s;
    g_csr_w[pos] = 0.9f * g_dis[s] * g_dis[d];
}

// ---- APPNP gather ----
__global__ void __launch_bounds__(256)
appnp_gather(const float* __restrict__ x, float* __restrict__ y) {
    long t = (long)blockIdx.x * blockDim.x + threadIdx.x;
    long n = t >> 3;
    int sub = (int)(t & 7);
    if (n >= NN_) return;
    int p0 = g_rowstart[n], p1 = g_rowstart[n + 1];
    const float4* x4 = (const float4*)x;
    float4 acc = make_float4(0.f, 0.f, 0.f, 0.f);
    for (int p = p0; p < p1; p++) {
        int s = g_csr_src[p];
        float w = g_csr_w[p];
        float4 xv = x4[(size_t)s * 8 + sub];
        acc.x += w * xv.x; acc.y += w * xv.y;
        acc.z += w * xv.z; acc.w += w * xv.w;
    }
    float sw = g_selfw[n];
    float4 xn = x4[(size_t)n * 8 + sub];
    float4 h = ((const float4*)g_gnn2)[(size_t)n * 8 + sub];
    float4 r;
    r.x = acc.x + sw * xn.x + 0.1f * h.x;
    r.y = acc.y + sw * xn.y + 0.1f * h.y;
    r.z = acc.z + sw * xn.z + 0.1f * h.z;
    r.w = acc.w + sw * xn.w + 0.1f * h.w;
    ((float4*)y)[(size_t)n * 8 + sub] = r;
}

__global__ void build_wcat(const float* __restrict__ qw, const float* __restrict__ kw,
                           const float* __restrict__ vw, const float* __restrict__ l1w,
                           const float* __restrict__ qb, const float* __restrict__ kb,
                           const float* __restrict__ vb, const float* __restrict__ l1b) {
    int idx = blockIdx.x * blockDim.x + threadIdx.x;
    if (idx >= 1024 * 256) return;
    int j = idx >> 8, k = idx & 255;
    const float* sw = (j < 256) ? qw : (j < 512) ? kw : (j < 768) ? vw : l1w;
    const float* sb = (j < 256) ? qb : (j < 512) ? kb : (j < 768) ? vb : l1b;
    g_Wcat[idx] = sw[(j & 255) * 256 + k];
    if (k == 0) g_bcat[j] = sb[j & 255];
}

// ---- SIMT NT GEMM (R3 inner loop) + global->reg double buffering ----
// MODE: 0 plain, 1 elu, 2 qkv-special (mirror cols>=768 to g_cat with elu)
template <int MODE>
__global__ void __launch_bounds__(128)
gemm_nt(const float* __restrict__ A, int lda, long sAz,
        const float* __restrict__ B, int ldb, long sBz,
        float* __restrict__ C, int ldc, long sCz,
        int M, int Ncols, int K, const float* __restrict__ bias, float alpha,
        unsigned* kmaxp) {
    __shared__ __align__(16) float As[16][132];
    __shared__ __align__(16) float Bs[16][68];
    __shared__ float red[128];
    int z = blockIdx.z;
    A += (long)z * sAz; B += (long)z * sBz; C += (long)z * sCz;
    int m0 = blockIdx.x * 128, n0 = blockIdx.y * 64;
    int tid = threadIdx.x, tx = tid & 7, ty = tid >> 3;
    int lr = tid >> 2, lk = (tid & 3) * 4;
    float acc[8][8];
#pragma unroll
    for (int j = 0; j < 8; j++)
#pragma unroll
        for (int i = 0; i < 8; i++) acc[j][i] = 0.f;

    float4 pa[4], pb[2];
#pragma unroll
    for (int p = 0; p < 4; p++) {
        int m = m0 + lr + 32 * p;
        pa[p] = make_float4(0, 0, 0, 0);
        if (m < M) pa[p] = *(const float4*)(A + (size_t)m * lda + lk);
    }
#pragma unroll
    for (int p = 0; p < 2; p++) {
        int n = n0 + lr + 32 * p;
        pb[p] = make_float4(0, 0, 0, 0);
        if (n < Ncols) pb[p] = *(const float4*)(B + (size_t)n * ldb + lk);
    }

    for (int k0 = 0; k0 < K; k0 += 16) {
#pragma unroll
        for (int p = 0; p < 4; p++) {
            As[lk][lr + 32 * p] = pa[p].x; As[lk + 1][lr + 32 * p] = pa[p].y;
            As[lk + 2][lr + 32 * p] = pa[p].z; As[lk + 3][lr + 32 * p] = pa[p].w;
        }
#pragma unroll
        for (int p = 0; p < 2; p++) {
            Bs[lk][lr + 32 * p] = pb[p].x; Bs[lk + 1][lr + 32 * p] = pb[p].y;
            Bs[lk + 2][lr + 32 * p] = pb[p].z; Bs[lk + 3][lr + 32 * p] = pb[p].w;
        }
        __syncthreads();
        if (k0 + 16 < K) {
            int kn = k0 + 16 + lk;
#pragma unroll
            for (int p = 0; p < 4; p++) {
                int m = m0 + lr + 32 * p;
                pa[p] = make_float4(0, 0, 0, 0);
                if (m < M) pa[p] = *(const float4*)(A + (size_t)m * lda + kn);
            }
#pragma unroll
            for (int p = 0; p < 2; p++) {
                int n = n0 + lr + 32 * p;
                pb[p] = make_float4(0, 0, 0, 0);
                if (n < Ncols) pb[p] = *(const float4*)(B + (size_t)n * ldb + kn);
            }
        }
#pragma unroll
        for (int k = 0; k < 16; k++) {
            float ra[8], rb[8];
#pragma unroll
            for (int j = 0; j < 8; j++) ra[j] = As[k][ty + 16 * j];
#pragma unroll
            for (int i = 0; i < 8; i++) rb[i] = Bs[k][tx + 8 * i];
#pragma unroll
            for (int j = 0; j < 8; j++)
#pragma unroll
                for (int i = 0; i < 8; i++) acc[j][i] += ra[j] * rb[i];
        }
        __syncthreads();
    }
    float mx = -INFINITY;
#pragma unroll
    for (int j = 0; j < 8; j++) {
        int m = m0 + ty + 16 * j;
        if (m >= M) continue;
#pragma unroll
        for (int i = 0; i < 8; i++) {
            int n = n0 + tx + 8 * i;
            if (n >= Ncols) continue;
            float v = acc[j][i] * alpha + (bias ? bias[n] : 0.f);
            if (MODE == 1) v = eluf(v);
            C[(size_t)m * ldc + n] = v;
            if (MODE == 2 && n >= 768)
                g_cat[(size_t)m * 512 + (n - 768)] = eluf(v);
            mx = fmaxf(mx, v);
        }
    }
    if (kmaxp && z >= 4) {
        red[tid] = mx;
        __syncthreads();
        for (int s = 64; s > 0; s >>= 1) {
            if (tid < s) red[tid] = fmaxf(red[tid], red[tid + s]);
            __syncthreads();
        }
        if (tid == 0) atomicMax(&kmaxp[z - 4], fenc(red[0]));
    }
}

__global__ void diag_kernel() {
    int gw = (blockIdx.x * blockDim.x + threadIdx.x) >> 5;
    int lane = threadIdx.x & 31;
    if (gw >= 8 * NN_) return;
    int s = gw / NN_, n = gw % NN_;
    const float* row = g_qkvg + (size_t)n * 1024 + s * 64;
    float v0 = row[lane], v1 = row[lane + 32];
    float sum = v0 * v0 + v1 * v1;
#pragma unroll
    for (int o = 16; o > 0; o >>= 1) sum += __shfl_xor_sync(~0u, sum, o);
    if (lane == 0) g_diag[s * NN_ + n] = 0.0625f * sum;
}

__global__ void qp_kernel() {
    int gw = (blockIdx.x * blockDim.x + threadIdx.x) >> 5;
    int lane = threadIdx.x & 31;
    if (gw >= 4 * NN_) return;
    int s = gw / NN_, n = gw % NN_;
    float* row = g_dd + (size_t)s * NN_ * MP + (size_t)n * MP;
    float dg = g_diag[s * NN_ + n];
    float vals[9], mx = -INFINITY;
#pragma unroll
    for (int i = 0; i < 9; i++) {
        int m = lane + 32 * i;
        float v = (m < MF) ? row[m] : -INFINITY;
        vals[i] = v; mx = fmaxf(mx, v);
    }
#pragma unroll
    for (int o = 16; o > 0; o >>= 1) mx = fmaxf(mx, __shfl_xor_sync(~0u, mx, o));
#pragma unroll
    for (int i = 0; i < 9; i++) {
        int m = lane + 32 * i;
        if (m < MP) row[m] = (m < MF) ? RATIO * (expf(vals[i] - dg - mx) + FEPS) : 0.f;
    }
}

__global__ void kmax_init() { if (threadIdx.x < 4) g_kmax[threadIdx.x] = 0x007FFFFFu; }

__global__ void kp_kernel() {
    int gw = (blockIdx.x * blockDim.x + threadIdx.x) >> 5;
    int lane = threadIdx.x & 31;
    if (gw >= 4 * NN_) return;
    int s = gw / NN_, n = gw % NN_;
    float* row = g_dd + (size_t)(4 + s) * NN_ * MP + (size_t)n * MP;
    float dg = g_diag[(4 + s) * NN_ + n];
    float mx = fdec(g_kmax[s]);
#pragma unroll
    for (int i = 0; i < 9; i++) {
        int m = lane + 32 * i;
        if (m < MP) row[m] = (m < MF) ? RATIO * (expf(row[m] - dg - mx) + FEPS) : 0.f;
    }
}

__global__ void zero_f(float* p, int n) {
    int i = blockIdx.x * blockDim.x + threadIdx.x;
    if (i < n) p[i] = 0.f;
}

// ---- ctx[h][m][j] = sum_n kp[h][n][m] * vext[n][j]; j==64 ones column ----
__global__ void __launch_bounds__(256)
ctx_kernel(int kchunk) {
    __shared__ __align__(16) float As[16][66];
    __shared__ __align__(16) float Bs[16][80];
    int h = blockIdx.z;
    const float* A = g_dd + (size_t)(4 + h) * NN_ * MP;
    int m0 = blockIdx.x * 64;
    int kb = blockIdx.y * kchunk, ke = min(kb + kchunk, NN_);
    int tid = threadIdx.x, tx = tid & 15, ty = tid >> 4;
    float acc[4][5];
#pragma unroll
    for (int a = 0; a < 4; a++)
#pragma unroll
        for (int b = 0; b < 5; b++) acc[a][b] = 0.f;
    for (int kk = kb; kk < ke; kk += 16) {
        {
            int k = tid >> 4, f = tid & 15;
            int kr = kk + k;
            float4 v = make_float4(0, 0, 0, 0);
            if (kr < ke && (m0 + 4 * f + 3) < MP)
                v = *(const float4*)(A + (size_t)kr * MP + m0 + 4 * f);
            As[k][4 * f] = v.x; As[k][4 * f + 1] = v.y;
            As[k][4 * f + 2] = v.z; As[k][4 * f + 3] = v.w;
        }
#pragma unroll
        for (int q = 0; q < 5; q++) {
            int fi = tid + 256 * q;
            int kr2 = fi / 80, j = fi % 80;
            int krow = kk + kr2;
            float v = 0.f;
            if (krow < ke) {
                if (j < 64) v = g_qkvg[(size_t)krow * 1024 + 512 + h * 64 + j];
                else if (j == 64) v = 1.f;
            }
            Bs[kr2][j] = v;
        }
        __syncthreads();
#pragma unroll
        for (int k2 = 0; k2 < 16; k2++) {
            float ra[4], rb[5];
#pragma unroll
            for (int a = 0; a < 4; a++) ra[a] = As[k2][ty * 4 + a];
#pragma unroll
            for (int b = 0; b < 5; b++) rb[b] = Bs[k2][tx * 5 + b];
#pragma unroll
            for (int a = 0; a < 4; a++)
#pragma unroll
                for (int b = 0; b < 5; b++) acc[a][b] += ra[a] * rb[b];
        }
        __syncthreads();
    }
    float* Cb = g_ctx + (size_t)h * 320 * 80;
#pragma unroll
    for (int a = 0; a < 4; a++)
#pragma unroll
        for (int b = 0; b < 5; b++)
            atomicAdd(&Cb[(m0 + ty * 4 + a) * 80 + tx * 5 + b], acc[a][b]);
}

// ---- attn = (qp @ ctx) / den -> elu -> g_cat[:,256+64h+c] (R3 version) ----
__global__ void __launch_bounds__(128)
gemm_attn() {
    __shared__ __align__(16) float As[16][68];
    __shared__ __align__(16) float Bs[16][80];
    __shared__ float sden[64];
    int h = blockIdx.z;
    const float* A = g_dd + (size_t)h * NN_ * MP;
    const float* B = g_ctx + (size_t)h * 320 * 80;
    int m0 = blockIdx.x * 64;
    int tid = threadIdx.x, tx = tid & 15, ty = tid >> 4;
    int lr = tid >> 2, lk = (tid & 3) * 4;
    float acc[8][5];
#pragma unroll
    for (int j = 0; j < 8; j++)
#pragma unroll
        for (int i = 0; i < 5; i++) acc[j][i] = 0.f;
    for (int k0 = 0; k0 < MP; k0 += 16) {
#pragma unroll
        for (int p = 0; p < 2; p++) {
            int m = m0 + lr + 32 * p;
            float4 v = make_float4(0, 0, 0, 0);
            if (m < NN_) v = *(const float4*)(A + (size_t)m * MP + k0 + lk);
            As[lk][lr + 32 * p] = v.x; As[lk + 1][lr + 32 * p] = v.y;
            As[lk + 2][lr + 32 * p] = v.z; As[lk + 3][lr + 32 * p] = v.w;
        }
#pragma unroll
        for (int q = 0; q < 3; q++) {
            int f4 = tid + 128 * q;
            if (f4 < 320)
                *(float4*)(&Bs[0][0] + f4 * 4) = *(const float4*)(B + (size_t)k0 * 80 + f4 * 4);
        }
        __syncthreads();
#pragma unroll
        for (int k = 0; k < 16; k++) {
            float ra[8], rb[5];
#pragma unroll
            for (int j = 0; j < 8; j++) ra[j] = As[k][ty + 8 * j];
#pragma unroll
            for (int i = 0; i < 5; i++) rb[i] = Bs[k][tx * 5 + i];
#pragma unroll
            for (int j = 0; j < 8; j++)
#pragma unroll
                for (int i = 0; i < 5; i++) acc[j][i] += ra[j] * rb[i];
        }
        __syncthreads();
    }
    if (tx == 12) {
#pragma unroll
        for (int j = 0; j < 8; j++) sden[ty + 8 * j] = acc[j][4];
    }
    __syncthreads();
#pragma unroll
    for (int j = 0; j < 8; j++) {
        int m = m0 + ty + 8 * j;
        if (m >= NN_) continue;
        float dinv = 1.f / sden[ty + 8 * j];
#pragma unroll
        for (int i = 0; i < 5; i++) {
            int c = tx * 5 + i;
            if (c < 64) g_cat[(size_t)m * 512 + 256 + h * 64 + c] = eluf(acc[j][i] * dinv);
        }
    }
}

__global__ void logsm_kernel(float* out, int wr2) {
    long gw = ((long)blockIdx.x * blockDim.x + threadIdx.x) >> 5;
    int lane = threadIdx.x & 31;
    if (gw >= NN_) return;
    float v = g_xb[gw * 32 + lane];
    float mx = v;
#pragma unroll
    for (int o = 16; o > 0; o >>= 1) mx = fmaxf(mx, __shfl_xor_sync(~0u, mx, o));
    float e = expf(v - mx), se = e;
#pragma unroll
    for (int o = 16; o > 0; o >>= 1) se += __shfl_xor_sync(~0u, se, o);
    out[gw * 32 + lane] = v - mx - logf(se);
    if (wr2) out[(size_t)NN_ * 32 + gw * 32 + lane] = v;
}

extern "C" void kernel_launch(void* const* d_in, const int* in_sizes, int n_in,
                              void* d_out, int out_size) {
    const float* x = (const float*)d_in[0];
    const void* ei = d_in[1];
    const float* l1w = (const float*)d_in[2];
    const float* l1b = (const float*)d_in[3];
    const float* l2w = (const float*)d_in[4];
    const float* l2b = (const float*)d_in[5];
    const float* qw = (const float*)d_in[6];
    const float* qb = (const float*)d_in[7];
    const float* kw = (const float*)d_in[8];
    const float* kb = (const float*)d_in[9];
    const float* vw = (const float*)d_in[10];
    const float* vb = (const float*)d_in[11];
    const float* proj = (const float*)d_in[12];
    float* out = (float*)d_out;

    float* d_Wcat; cudaGetSymbolAddress((void**)&d_Wcat, g_Wcat);
    float* d_bcat; cudaGetSymbolAddress((void**)&d_bcat, g_bcat);
    float* d_qkvg; cudaGetSymbolAddress((void**)&d_qkvg, g_qkvg);
    float* d_dd; cudaGetSymbolAddress((void**)&d_dd, g_dd);
    float* d_ctx; cudaGetSymbolAddress((void**)&d_ctx, g_ctx);
    float* d_cat; cudaGetSymbolAddress((void**)&d_cat, g_cat);
    float* d_gnn2; cudaGetSymbolAddress((void**)&d_gnn2, g_gnn2);
    float* d_xa; cudaGetSymbolAddress((void**)&d_xa, g_xa);
    float* d_xb; cudaGetSymbolAddress((void**)&d_xb, g_xb);
    int* d_cnt; cudaGetSymbolAddress((void**)&d_cnt, g_cnt);
    int* d_cur; cudaGetSymbolAddress((void**)&d_cur, g_cur);
    unsigned* d_kmax; cudaGetSymbolAddress((void**)&d_kmax, g_kmax);

    // graph prep
    sniff_edges<<<1, 32>>>(ei);
    zero_i<<<(NN_ + 255) / 256, 256>>>(d_cnt, NN_);
    zero_i<<<(NN_ + 255) / 256, 256>>>(d_cur, NN_);
    conv_edges<<<(NE_ + 255) / 256, 256>>>(ei);
    scan1<<<NCHUNK, 1024>>>();
    scan2<<<1, 128>>>();
    scan3<<<(NN_ + 255) / 256, 256>>>();
    dis_kernel<<<(NN_ + 255) / 256, 256>>>();
    fill_csr<<<(NE_ + 255) / 256, 256>>>();

    // dense pipeline
    build_wcat<<<(1024 * 256 + 255) / 256, 256>>>(qw, kw, vw, l1w, qb, kb, vb, l1b);
    gemm_nt<2><<<dim3((NN_ + 127) / 128, 16, 1), 128>>>(
        x, 256, 0, d_Wcat, 256, 0, d_qkvg, 1024, 0, NN_, 1024, 256, d_bcat, 1.f, nullptr);
    kmax_init<<<1, 32>>>();
    gemm_nt<0><<<dim3((NN_ + 127) / 128, 5, 8), 128>>>(
        d_qkvg, 1024, 64, proj, 64, 0, d_dd, MP, (long)NN_ * MP, NN_, MF, 64, nullptr,
        DN_SCALE, d_kmax);
    diag_kernel<<<(8L * NN_ * 32 + 255) / 256, 256>>>();
    qp_kernel<<<(4L * NN_ * 32 + 255) / 256, 256>>>();
    kp_kernel<<<(4L * NN_ * 32 + 255) / 256, 256>>>();
    zero_f<<<(4 * 320 * 80 + 255) / 256, 256>>>(d_ctx, 4 * 320 * 80);
    int kchunk = (NN_ + 63) / 64;
    ctx_kernel<<<dim3(5, 64, 4), 256>>>(kchunk);
    gemm_attn<<<dim3((NN_ + 63) / 64, 1, 4), 128>>>();
    gemm_nt<1><<<dim3((NN_ + 127) / 128, 1, 1), 128>>>(
        d_cat, 512, 0, l2w, 512, 0, d_gnn2, 32, 0, NN_, 32, 512, l2b, 1.f, nullptr);

    // APPNP
    long nth = (long)NN_ * 8;
    const float* cur = d_gnn2;
    float* nxt = d_xa;
    for (int it = 0; it < 10; it++) {
        appnp_gather<<<(nth + 255) / 256, 256>>>(cur, nxt);
        if (it == 0) { cur = d_xa; nxt = d_xb; }
        else { const float* t = cur; cur = nxt; nxt = (float*)t; }
    }
    int wr2 = (out_size >= 2 * NN_ * 32) ? 1 : 0;
    logsm_kernel<<<((long)NN_ * 32 + 255) / 256, 256>>>(out, wr2);
}